// round 1
// baseline (speedup 1.0000x reference)
#include <cuda_runtime.h>
#include <cuda_fp16.h>

#define B_      2048
#define ADIM    14
#define C_      128
#define H_      256
#define E_      182
#define NNODES  (B_*ADIM)   /* 28672 */
#define NROWS   (B_*E_)     /* 372736 */

// ---------------- device scratch (no allocs allowed) ----------------
__device__ __half g_W2h [H_*H_];        // lin2_w fp16, row-major (g, h)
__device__ __half g_Wcat[512*C_];       // [o<256: W_left rows | o>=256: W_right rows], k-contig
__device__ __half g_Xh  [NNODES*C_];    // x = g + state, fp16
__device__ float  g_Y   [NNODES*512];   // per-node [yl(256) | yr(256)]

// ---------------- mma helpers ----------------
__device__ __forceinline__ void ldsm_x4(unsigned &r0,unsigned &r1,unsigned &r2,unsigned &r3, unsigned a){
  asm volatile("ldmatrix.sync.aligned.m8n8.x4.shared.b16 {%0,%1,%2,%3},[%4];"
    :"=r"(r0),"=r"(r1),"=r"(r2),"=r"(r3):"r"(a));
}
__device__ __forceinline__ void ldsm_x2(unsigned &r0,unsigned &r1, unsigned a){
  asm volatile("ldmatrix.sync.aligned.m8n8.x2.shared.b16 {%0,%1},[%2];"
    :"=r"(r0),"=r"(r1):"r"(a));
}
__device__ __forceinline__ void mma16816(float c[4], const unsigned a[4], const unsigned b[2]){
  asm volatile("mma.sync.aligned.m16n8k16.row.col.f32.f16.f16.f32 "
    "{%0,%1,%2,%3},{%4,%5,%6,%7},{%8,%9},{%0,%1,%2,%3};"
    :"+f"(c[0]),"+f"(c[1]),"+f"(c[2]),"+f"(c[3])
    :"r"(a[0]),"r"(a[1]),"r"(a[2]),"r"(a[3]),"r"(b[0]),"r"(b[1]));
}
__device__ __forceinline__ float lky(float v){ return v > 0.f ? v : 0.01f*v; }
__device__ __forceinline__ float softplus_(float x){ return fmaxf(x,0.f) + log1pf(expf(-fabsf(x))); }

// ---------------- K0: weight conversion ----------------
__global__ void k_prep(const float* __restrict__ lin1_w, const float* __restrict__ lin2_w){
  int i = blockIdx.x*blockDim.x + threadIdx.x;   // 65536 threads
  if (i < H_*H_) g_W2h[i] = __float2half(lin2_w[i]);
  if (i < 512*C_){
    int o = i >> 7, c = i & 127;
    float v = (o < H_) ? lin1_w[o*(2*C_) + c] : lin1_w[(o-H_)*(2*C_) + C_ + c];
    g_Wcat[i] = __float2half(v);
  }
}

// ---------------- K1: s_bar -> g -> X (8 batches per block) ----------------
__global__ __launch_bounds__(256,1)
void k1_build(const float* __restrict__ state, const float* __restrict__ conv_w,
              const float* __restrict__ conv_b){
  extern __shared__ float sm1[];
  float* cw   = sm1;                 // 128 x 129 (pad: conflict-free dot)
  float* sbar = cw + 128*129;        // 8 x 128
  float* gg   = sbar + 8*128;        // 8 x 128
  int tid = threadIdx.x;
  int b0  = blockIdx.x * 8;

  for (int i = tid; i < 128*128; i += 256){ int r = i>>7, c = i&127; cw[r*129+c] = conv_w[i]; }
  for (int idx = tid; idx < 8*128; idx += 256){
    int bb = idx >> 7, c = idx & 127;
    const float* sp = state + (size_t)(b0+bb)*ADIM*C_ + c;
    float s = 0.f;
    #pragma unroll
    for (int i = 0; i < ADIM; i++) s += sp[i*C_];
    sbar[idx] = s * (1.0f/14.0f);
  }
  __syncthreads();
  #pragma unroll
  for (int u = 0; u < 4; u++){
    int o = tid + u*256;             // 1024 = 8 batches * 128 outputs
    int bb = o >> 7, h = o & 127;
    const float* sb = sbar + bb*128;
    const float* w  = cw + h*129;
    float acc = 0.f;
    #pragma unroll 8
    for (int c = 0; c < 128; c++) acc += sb[c]*w[c];
    gg[o] = fmaxf(acc + conv_b[h], 0.f);
  }
  __syncthreads();
  for (int idx = tid; idx < 8*ADIM*C_; idx += 256){
    int bb = idx / (ADIM*C_); int rem = idx - bb*(ADIM*C_);
    int c  = rem & 127;
    size_t node = (size_t)(b0+bb)*ADIM + (rem >> 7);
    g_Xh[node*C_ + c] = __float2half(gg[bb*128 + c] + state[node*C_ + c]);
  }
}

// ---------------- K2: Y = X(28672x128) @ Wcat^T(128x512), fp16 mma ----------------
__global__ __launch_bounds__(256,1)
void k2_ygemm(){
  extern __shared__ __half sm2[];
  __half* As = sm2;             // 128 x 136 (pad 8)
  __half* Bs = As + 128*136;    // 128 x 136
  int tid = threadIdx.x;
  int m0 = blockIdx.x * 128, n0 = blockIdx.y * 128;

  for (int idx = tid; idx < 128*16; idx += 256){
    int r = idx >> 4, c = idx & 15;
    *(uint4*)&As[r*136 + c*8] = *(const uint4*)&g_Xh [(size_t)(m0+r)*C_ + c*8];
    *(uint4*)&Bs[r*136 + c*8] = *(const uint4*)&g_Wcat[(size_t)(n0+r)*C_ + c*8];
  }
  __syncthreads();

  int lane = tid & 31, warp = tid >> 5, wm = warp >> 2, wn = warp & 3;
  unsigned abase = (unsigned)__cvta_generic_to_shared(As);
  unsigned bbase = (unsigned)__cvta_generic_to_shared(Bs);
  float acc[4][4][4];
  #pragma unroll
  for (int i=0;i<4;i++) for (int j=0;j<4;j++) for (int q=0;q<4;q++) acc[i][j][q]=0.f;

  int rA = (lane & 7) + ((lane >> 3) & 1) * 8;
  int cA = (lane >> 4) * 8;
  int l16 = lane & 15;
  int rB = l16 & 7;
  int cB = (l16 >> 3) * 8;

  #pragma unroll
  for (int kk = 0; kk < 8; kk++){
    int k0 = kk*16;
    unsigned a[4][4], b[4][2];
    #pragma unroll
    for (int mi = 0; mi < 4; mi++){
      int row = wm*64 + mi*16 + rA;
      ldsm_x4(a[mi][0],a[mi][1],a[mi][2],a[mi][3], abase + (row*136 + k0 + cA)*2);
    }
    #pragma unroll
    for (int ni = 0; ni < 4; ni++){
      int row = wn*32 + ni*8 + rB;
      ldsm_x2(b[ni][0],b[ni][1], bbase + (row*136 + k0 + cB)*2);
    }
    #pragma unroll
    for (int mi = 0; mi < 4; mi++)
      #pragma unroll
      for (int ni = 0; ni < 4; ni++)
        mma16816(acc[mi][ni], a[mi], b[ni]);
  }
  #pragma unroll
  for (int mi = 0; mi < 4; mi++)
    #pragma unroll
    for (int ni = 0; ni < 4; ni++){
      int row = m0 + wm*64 + mi*16 + (lane >> 2);
      int col = n0 + wn*32 + ni*8 + ((lane & 3) << 1);
      *(float2*)&g_Y[(size_t)row*512 + col]     = make_float2(acc[mi][ni][0], acc[mi][ni][1]);
      *(float2*)&g_Y[(size_t)(row+8)*512 + col] = make_float2(acc[mi][ni][2], acc[mi][ni][3]);
    }
}

// ---------------- K3: fused per-batch H1 build + lin2 GEMM + heads ----------------
// persistent CTAs; W2 (fp16, padded) resident in smem
__global__ __launch_bounds__(256,1)
void k3_main(const float* __restrict__ lin1_b, const float* __restrict__ lin2_b,
             const float* __restrict__ mu_w,  const float* __restrict__ mu_b,
             const float* __restrict__ sig_w, const float* __restrict__ sig_b,
             const float* __restrict__ noise, float* __restrict__ out){
  extern __shared__ float sm3[];
  float*  Ys    = sm3;                  // 14 x 512
  float*  b1s   = Ys + ADIM*512;        // 256
  float*  redmu = b1s + 256;            // 96 x 4
  float*  redsg = redmu + 96*4;         // 96 x 4
  float*  lp    = redsg + 96*4;         // 1 (+3 pad)
  __half* W2s   = (__half*)(lp + 4);    // 256 x 264
  __half* H1s   = W2s + 256*264;        // 96 x 264

  int tid  = threadIdx.x;
  int lane = tid & 31, warp = tid >> 5;
  int warp_m = warp >> 2, warp_n = warp & 3;

  // one-time: W2 + b1 into smem
  for (int i = tid; i < 256; i += 256) b1s[i] = lin1_b[i];
  for (int idx = tid; idx < 256*32; idx += 256){
    int r = idx >> 5, c = idx & 31;
    *(uint4*)&W2s[r*264 + c*8] = ((const uint4*)g_W2h)[r*32 + c];
  }
  // per-thread column constants (cols fixed for CTA lifetime)
  float wmu[8][2], wsg[8][2], wb2[8][2];
  #pragma unroll
  for (int ni = 0; ni < 8; ni++){
    int n = warp_n*64 + ni*8 + ((lane & 3) << 1);
    wmu[ni][0] = mu_w[n];   wmu[ni][1] = mu_w[n+1];
    wsg[ni][0] = sig_w[n];  wsg[ni][1] = sig_w[n+1];
    wb2[ni][0] = lin2_b[n]; wb2[ni][1] = lin2_b[n+1];
  }
  float mub = mu_b[0], sgb = sig_b[0];
  __syncthreads();

  unsigned h1b = (unsigned)__cvta_generic_to_shared(H1s);
  unsigned w2b = (unsigned)__cvta_generic_to_shared(W2s);
  int rA = (lane & 7) + ((lane >> 3) & 1) * 8;
  int cA = (lane >> 4) * 8;
  int l16 = lane & 15;
  int rBo = l16 & 7;
  int cB  = (l16 >> 3) * 8;

  for (int b = blockIdx.x; b < B_; b += gridDim.x){
    // stage Y[b] (14 x 512)
    {
      const float4* ysrc = (const float4*)(g_Y + (size_t)b*ADIM*512);
      float4* ydst = (float4*)Ys;
      for (int i = tid; i < ADIM*128; i += 256) ydst[i] = ysrc[i];
      if (tid == 0) lp[0] = 0.f;
    }
    __syncthreads();

    #pragma unroll
    for (int chunk = 0; chunk < 2; chunk++){
      // ---- prologue: H1 rows (96 x 256) fp16 ----
      for (int idx = tid; idx < 96*32; idx += 256){
        int m  = idx >> 5;
        int hb = (idx & 31) << 3;
        int e  = chunk*96 + m;
        union { uint4 u4; __half2 h2[4]; } P;
        if (e < E_){
          int ii = e/13; int r = e - ii*13; int jj = r + (r >= ii ? 1 : 0);
          const float* yl = Ys + ii*512 + hb;
          const float* yr = Ys + jj*512 + 256 + hb;
          const float* bp = b1s + hb;
          float v[8];
          #pragma unroll
          for (int q = 0; q < 8; q++) v[q] = lky(yl[q] + yr[q] + bp[q]);
          P.h2[0] = __floats2half2_rn(v[0], v[1]);
          P.h2[1] = __floats2half2_rn(v[2], v[3]);
          P.h2[2] = __floats2half2_rn(v[4], v[5]);
          P.h2[3] = __floats2half2_rn(v[6], v[7]);
        } else {
          P.u4 = make_uint4(0u,0u,0u,0u);
        }
        *(uint4*)&H1s[m*264 + hb] = P.u4;
      }
      __syncthreads();

      // ---- GEMM: (96 x 256) @ W2^T ----
      float acc[3][8][4];
      #pragma unroll
      for (int i=0;i<3;i++) for (int j=0;j<8;j++) for (int q=0;q<4;q++) acc[i][j][q]=0.f;

      #pragma unroll
      for (int kk = 0; kk < 16; kk++){
        int k0 = kk*16;
        unsigned a[3][4], bf[8][2];
        #pragma unroll
        for (int mi = 0; mi < 3; mi++){
          int row = warp_m*48 + mi*16 + rA;
          ldsm_x4(a[mi][0],a[mi][1],a[mi][2],a[mi][3], h1b + (row*264 + k0 + cA)*2);
        }
        #pragma unroll
        for (int ni = 0; ni < 8; ni++){
          int row = warp_n*64 + ni*8 + rBo;
          ldsm_x2(bf[ni][0],bf[ni][1], w2b + (row*264 + k0 + cB)*2);
        }
        #pragma unroll
        for (int mi = 0; mi < 3; mi++)
          #pragma unroll
          for (int ni = 0; ni < 8; ni++)
            mma16816(acc[mi][ni], a[mi], bf[ni]);
      }

      // ---- epilogue: +b2, leaky, dot with mu_w/sig_w, reduce ----
      #pragma unroll
      for (int mi = 0; mi < 3; mi++){
        float pm0=0.f, ps0=0.f, pm1=0.f, ps1=0.f;
        #pragma unroll
        for (int ni = 0; ni < 8; ni++){
          float v0 = lky(acc[mi][ni][0] + wb2[ni][0]);
          float v1 = lky(acc[mi][ni][1] + wb2[ni][1]);
          float v2 = lky(acc[mi][ni][2] + wb2[ni][0]);
          float v3 = lky(acc[mi][ni][3] + wb2[ni][1]);
          pm0 += v0*wmu[ni][0] + v1*wmu[ni][1];
          ps0 += v0*wsg[ni][0] + v1*wsg[ni][1];
          pm1 += v2*wmu[ni][0] + v3*wmu[ni][1];
          ps1 += v2*wsg[ni][0] + v3*wsg[ni][1];
        }
        pm0 += __shfl_xor_sync(0xffffffffu, pm0, 1); pm0 += __shfl_xor_sync(0xffffffffu, pm0, 2);
        ps0 += __shfl_xor_sync(0xffffffffu, ps0, 1); ps0 += __shfl_xor_sync(0xffffffffu, ps0, 2);
        pm1 += __shfl_xor_sync(0xffffffffu, pm1, 1); pm1 += __shfl_xor_sync(0xffffffffu, pm1, 2);
        ps1 += __shfl_xor_sync(0xffffffffu, ps1, 1); ps1 += __shfl_xor_sync(0xffffffffu, ps1, 2);
        if ((lane & 3) == 0){
          int row = warp_m*48 + mi*16 + (lane >> 2);
          redmu[row*4 + warp_n]     = pm0;  redsg[row*4 + warp_n]     = ps0;
          redmu[(row+8)*4 + warp_n] = pm1;  redsg[(row+8)*4 + warp_n] = ps1;
        }
      }
      __syncthreads();

      if (tid < 96){
        int e = chunk*96 + tid;
        if (e < E_){
          float mp = redmu[tid*4] + redmu[tid*4+1] + redmu[tid*4+2] + redmu[tid*4+3] + mub;
          float sp = redsg[tid*4] + redsg[tid*4+1] + redsg[tid*4+2] + redsg[tid*4+3] + sgb;
          float mu = softplus_(mp);
          float sd = softplus_(sp);
          float nz = noise[(size_t)b*E_ + e];
          out[(size_t)b*E_ + e] = mu + sd*nz;
          atomicAdd(lp, -0.5f*nz*nz - logf(sd));
        }
      }
      __syncthreads();
    }
    if (tid == 0) out[(size_t)NROWS + b] = lp[0] - (float)E_ * 0.91893853320467274f;
    __syncthreads();
  }
}

// ---------------- host launcher ----------------
extern "C" void kernel_launch(void* const* d_in, const int* in_sizes, int n_in,
                              void* d_out, int out_size){
  const float* state  = (const float*)d_in[0];
  const float* conv_w = (const float*)d_in[1];
  const float* conv_b = (const float*)d_in[2];
  const float* lin1_w = (const float*)d_in[3];
  const float* lin1_b = (const float*)d_in[4];
  const float* lin2_w = (const float*)d_in[5];
  const float* lin2_b = (const float*)d_in[6];
  const float* mu_w   = (const float*)d_in[7];
  const float* mu_b   = (const float*)d_in[8];
  const float* sig_w  = (const float*)d_in[9];
  const float* sig_b  = (const float*)d_in[10];
  const float* noise  = (const float*)d_in[11];
  float* out = (float*)d_out;

  const int SM1 = (128*129 + 8*128 + 8*128) * 4;                 // 74240
  const int SM2 = 2 * 128*136 * 2;                               // 69632
  const int SM3 = (ADIM*512 + 256 + 96*4*2 + 4) * 4 + (256*264 + 96*264) * 2; // 218640

  cudaFuncSetAttribute(k1_build, cudaFuncAttributeMaxDynamicSharedMemorySize, SM1);
  cudaFuncSetAttribute(k2_ygemm, cudaFuncAttributeMaxDynamicSharedMemorySize, SM2);
  cudaFuncSetAttribute(k3_main,  cudaFuncAttributeMaxDynamicSharedMemorySize, SM3);

  k_prep<<<256, 256>>>(lin1_w, lin2_w);
  k1_build<<<256, 256, SM1>>>(state, conv_w, conv_b);
  k2_ygemm<<<dim3(224, 4), 256, SM2>>>();
  k3_main<<<152, 256, SM3>>>(lin1_b, lin2_b, mu_w, mu_b, sig_w, sig_b, noise, out);
}